// round 7
// baseline (speedup 1.0000x reference)
#include <cuda_runtime.h>
#include <math.h>
#include <stdint.h>

#define B_    64
#define T_    1000
#define D_    512
#define V_    29
#define L_    200
#define S_    401            // 2*L + 1
#define CBLANK 28
#define NEGV  (-1e9f)
#define LOG2E 1.44269504088896340736f
#define LN2   0.69314718055994530942f

typedef unsigned long long u64;

// ---------------- device scratch (no allocations allowed) ----------------
__device__ float d_lp[(long)B_ * T_ * V_];   // LOG2-probs lp2[b][t][v], 7.4 MB
__device__ float d_loss[B_];

__device__ __forceinline__ float ex2f(float x){ float r; asm("ex2.approx.f32 %0, %1;" : "=f"(r) : "f"(x)); return r; }
__device__ __forceinline__ float lg2f(float x){ float r; asm("lg2.approx.f32 %0, %1;" : "=f"(r) : "f"(x)); return r; }

// exact 3-way log2-sum-exp via selects (no cancellation; NEGV-safe)
__device__ __forceinline__ float lse3(float a0, float a1, float a2)
{
    const float mab = fmaxf(a0, a1);
    const float nab = fminf(a0, a1);
    const float mx  = fmaxf(mab, a2);
    const float mn  = fminf(nab, a2);
    const float md  = fmaxf(nab, fminf(mab, a2));
    return mx + lg2f(1.0f + ex2f(mn - mx) + ex2f(md - mx));
}

__device__ __forceinline__ void st_release_shared(uint32_t addr, int v)
{
    asm volatile("st.release.cta.shared.b32 [%0], %1;" :: "r"(addr), "r"(v) : "memory");
}
__device__ __forceinline__ int ld_acquire_shared(uint32_t addr)
{
    int v;
    asm volatile("ld.acquire.cta.shared.b32 %0, [%1];" : "=r"(v) : "r"(addr) : "memory");
    return v;
}

#define FMA2(d, a, b) asm("fma.rn.f32x2 %0, %1, %2, %0;" : "+l"(d) : "l"(a), "l"(b))

// =====================================================================
// Kernel 1: logits = F @ W + b, log2_softmax, write d_lp.
// 256 threads, BM=256 rows/block (grid=250), thread tile 8 rows x 4 cols.
// F: cp.async double-buffered, row-major, XOR-swizzled smem (no transpose).
// W: whole 512x32 transposed wT[col][k] (stride 516), resident in smem.
// FFMA2 pairs over k (lo=even-k, hi=odd-k partial sums).
// FIX vs R4: mainloop W read now includes the kci*32 chunk offset.
// =====================================================================
#define BM2 256
#define WT_STRIDE 516
#define SMEM_GEMM_BYTES 132608

extern __shared__ char smem_dyn[];

__global__ __launch_bounds__(256, 1) void gemm_lsm_kernel(
    const float* __restrict__ F, const float* __restrict__ W,
    const float* __restrict__ bias)
{
    float* fbuf = (float*)smem_dyn;
    float* wT   = (float*)(smem_dyn + 65536);
    float* csh  = (float*)(smem_dyn + 131584);
    float* lbuf = fbuf;                         // epilogue reuse

    const int tid = threadIdx.x;
    const long rowBase = (long)blockIdx.x * BM2;
    const uint32_t fsh = (uint32_t)__cvta_generic_to_shared(fbuf);

    auto prefetch = [&](int kci, int st) {
        const uint32_t sbase = fsh + st * 32768u;
#pragma unroll
        for (int m = 0; m < 8; m++) {
            const int q  = tid + 256 * m;
            const int r  = q >> 3;
            const int kq = q & 7;
            const float* src = F + (rowBase + r) * D_ + kci * 32 + kq * 4;
            const uint32_t dst = sbase + (uint32_t)((r * 32 + ((kq ^ ((r >> 3) & 7)) << 2)) * 4);
            asm volatile("cp.async.ca.shared.global [%0], [%1], 16;" :: "r"(dst), "l"(src));
        }
    };

    prefetch(0, 0);
    asm volatile("cp.async.commit_group;");

    // one-time W transpose load (overlaps the first F prefetch)
    for (int idx = tid; idx < 512 * 32; idx += 256) {
        const int k = idx >> 5, c = idx & 31;
        wT[c * WT_STRIDE + k] = (c < V_) ? W[(long)k * V_ + c] : 0.f;
    }

    const int rg = tid >> 3;
    const int cg = tid & 7;
    const int fkey = (rg & 7) << 2;

    float bv[4];
#pragma unroll
    for (int j = 0; j < 4; j++) { int c = cg + 8 * j; bv[j] = (c < V_) ? bias[c] : 0.f; }

    u64 acc[8][4];
#pragma unroll
    for (int i = 0; i < 8; i++)
#pragma unroll
        for (int j = 0; j < 4; j++) acc[i][j] = 0ull;

    for (int kci = 0; kci < 16; kci++) {
        if (kci < 15) prefetch(kci + 1, (kci + 1) & 1);
        asm volatile("cp.async.commit_group;");
        asm volatile("cp.async.wait_group 1;");
        __syncthreads();

        const float* fstage = fbuf + (kci & 1) * 8192;
        const float* wbase  = wT + kci * 32;            // <<< THE FIX
#pragma unroll
        for (int kq = 0; kq < 8; kq++) {
            ulonglong2 f[8], w4[4];
#pragma unroll
            for (int i = 0; i < 8; i++)
                f[i] = *reinterpret_cast<const ulonglong2*>(
                    fstage + (rg * 8 + i) * 32 + ((kq << 2) ^ fkey));
#pragma unroll
            for (int j = 0; j < 4; j++)
                w4[j] = *reinterpret_cast<const ulonglong2*>(
                    wbase + (cg + 8 * j) * WT_STRIDE + kq * 4);
#pragma unroll
            for (int i = 0; i < 8; i++)
#pragma unroll
                for (int j = 0; j < 4; j++) FMA2(acc[i][j], f[i].x, w4[j].x);
#pragma unroll
            for (int i = 0; i < 8; i++)
#pragma unroll
                for (int j = 0; j < 4; j++) FMA2(acc[i][j], f[i].y, w4[j].y);
        }
        __syncthreads();
    }

    // ---- epilogue: combine k-pairs, bias, logits to smem [256][33] ----
#pragma unroll
    for (int i = 0; i < 8; i++)
#pragma unroll
        for (int j = 0; j < 4; j++) {
            const float lo = __uint_as_float((unsigned)(acc[i][j] & 0xffffffffull));
            const float hi = __uint_as_float((unsigned)(acc[i][j] >> 32));
            lbuf[(rg * 8 + i) * 33 + (cg + 8 * j)] = lo + hi + bv[j];
        }
    __syncthreads();

    // per-row (max*LOG2E + log2(sumexp)); thread <-> row
    {
        const float* r = &lbuf[tid * 33];
        float m = r[0];
#pragma unroll
        for (int v = 1; v < V_; v++) m = fmaxf(m, r[v]);
        float sum = 0.f;
#pragma unroll
        for (int v = 0; v < V_; v++) sum += ex2f((r[v] - m) * LOG2E);
        csh[tid] = m * LOG2E + lg2f(sum);
    }
    __syncthreads();

    // coalesced write of LOG2-probs
    float* outp = d_lp + rowBase * V_;
    for (int i = tid; i < BM2 * V_; i += 256) {
        const int row = i / V_;
        const int v   = i - row * V_;
        outp[i] = lbuf[row * 33 + v] * LOG2E - csh[row];
    }
}

// =====================================================================
// Kernel 2: CTC alpha recursion, LOG2 domain, SKEWED WAVEFRONT with
// release/acquire ordering. One block per batch, 416 threads (13 warps),
// thread s owns state s, NO block barriers in the loop.
// Producer (lane 31 of warp w): st.shared.v2 {a30,a31} into 64-slot ring,
// then st.release counter = t. Consumer (warp w+1): ld.acquire poll on
// counter, then plain v2 read. 64-bit data, ordering via release/acquire
// -> no 128-bit atomicity assumption. Back-pressure keeps skew <= 48.
// =====================================================================
__global__ __launch_bounds__(416) void ctc_kernel(
    const int* __restrict__ labels, const int* __restrict__ flens,
    const int* __restrict__ llens)
{
    __shared__ float2 ring[13][64];     // [w][t&63] = {a[32w+30], a[32w+31]} at step t
    __shared__ int    cnt[13];          // last published step per warp (release)
    __shared__ int    lab_sh[L_];
    __shared__ float  afin[416];

    const int b    = blockIdx.x;
    const int tid  = threadIdx.x;
    const int w    = tid >> 5;
    const int lane = tid & 31;
    const int flen = flens[b];
    const int llen = llens[b];
    const unsigned FULL = 0xffffffffu;

    for (int i = tid; i < L_; i += 416) lab_sh[i] = labels[b * L_ + i];
    if (tid < 13) cnt[tid] = -1;
    __syncthreads();

    const int s = tid;
    int   ext  = CBLANK;
    bool  skip = false;
    if (s < S_ && (s & 1)) {
        const int j = s >> 1;
        ext  = lab_sh[j];
        skip = (s >= 3) ? (ext != lab_sh[j - 1]) : true;
    }

    const float* lpb = d_lp + (long)b * T_ * V_;

    const uint32_t cnt_sh  = (uint32_t)__cvta_generic_to_shared(cnt);
    const uint32_t myCnt   = cnt_sh + (uint32_t)w * 4u;
    const uint32_t prvCnt  = cnt_sh + (uint32_t)(w - 1) * 4u;
    volatile int* vcnt = cnt;

    // t = 0 init + publish
    float myA = NEGV;
    if (s == 0) myA = lpb[CBLANK];
    else if (s == 1) myA = lpb[ext];
    {
        const float a30 = __shfl_sync(FULL, myA, 30);
        if (lane == 31) {
            if (w < 12) ring[w][0] = make_float2(a30, myA);
            st_release_shared(myCnt, 0);
        }
    }

    // 8-deep per-thread lp prefetch: pf_k holds row t+k at loop entry (t=1)
    float pf0 = lpb[1 * V_ + ext];
    float pf1 = lpb[2 * V_ + ext];
    float pf2 = lpb[3 * V_ + ext];
    float pf3 = lpb[4 * V_ + ext];
    float pf4 = lpb[5 * V_ + ext];
    float pf5 = lpb[6 * V_ + ext];
    float pf6 = lpb[7 * V_ + ext];
    float pf7 = lpb[8 * V_ + ext];

    int t = 1;

#define CTC_STEP(PF) do {                                                        \
    float bx = NEGV, by = NEGV;                                                  \
    if (w > 0) {                                                                 \
        while (ld_acquire_shared(prvCnt) < t - 1) { }                            \
        const float2 d = ring[w - 1][(t - 1) & 63];                              \
        by = d.x; bx = d.y;                                                      \
    }                                                                            \
    float am1 = __shfl_up_sync(FULL, myA, 1);                                    \
    float am2 = __shfl_up_sync(FULL, myA, 2);                                    \
    if (lane == 0) { am1 = bx; am2 = by; }                                       \
    else if (lane == 1) { am2 = bx; }                                            \
    myA = lse3(myA, am1, skip ? am2 : NEGV) + PF;                                \
    PF = lpb[min(t + 8, T_ - 1) * V_ + ext];                                     \
    {                                                                            \
        const float a30 = __shfl_sync(FULL, myA, 30);                            \
        if (lane == 31) {                                                        \
            if (w < 12) ring[w][t & 63] = make_float2(a30, myA);                 \
            st_release_shared(myCnt, t);                                         \
        }                                                                        \
    }                                                                            \
    if ((t & 15) == 0 && w < 12) {                                               \
        while (vcnt[w + 1] < t - 32) { }                                         \
    }                                                                            \
    t++;                                                                         \
} while (0)

    while (t + 7 < flen) {
        CTC_STEP(pf0); CTC_STEP(pf1); CTC_STEP(pf2); CTC_STEP(pf3);
        CTC_STEP(pf4); CTC_STEP(pf5); CTC_STEP(pf6); CTC_STEP(pf7);
    }
    while (t < flen) {
        CTC_STEP(pf0);
        pf0 = pf1; pf1 = pf2; pf2 = pf3; pf3 = pf4;
        pf4 = pf5; pf5 = pf6; pf6 = pf7;
    }
#undef CTC_STEP

    __syncthreads();
    afin[tid] = myA;
    __syncthreads();

    if (tid == 0) {
        const float l1 = afin[2 * llen];        // alpha[2*llen]   (llen >= 50)
        const float l2 = afin[2 * llen - 1];    // alpha[2*llen-1]
        const float mx = fmaxf(l1, l2), mn = fminf(l1, l2);
        const float ls = mx + lg2f(1.0f + ex2f(mn - mx));
        const float nll = -ls * LN2;
        d_loss[b] = (nll < 5e8f) ? nll / (float)llen : 0.f;
    }
}

// =====================================================================
// Kernel 3: deterministic fixed-order mean of 64 losses
// =====================================================================
__global__ void reduce_kernel(float* __restrict__ out)
{
    const int lane = threadIdx.x;
    float v = d_loss[lane] + d_loss[lane + 32];
#pragma unroll
    for (int o = 16; o > 0; o >>= 1) v += __shfl_down_sync(0xffffffffu, v, o);
    if (lane == 0) out[0] = v * (1.f / (float)B_);
}

// =====================================================================
extern "C" void kernel_launch(void* const* d_in, const int* in_sizes, int n_in,
                              void* d_out, int out_size)
{
    (void)in_sizes; (void)n_in; (void)out_size;
    const float* F      = (const float*)d_in[0];
    const float* W      = (const float*)d_in[1];
    const float* bias   = (const float*)d_in[2];
    const int*   labels = (const int*)d_in[3];
    const int*   flens  = (const int*)d_in[4];
    const int*   llens  = (const int*)d_in[5];
    float* out = (float*)d_out;

    cudaFuncSetAttribute(gemm_lsm_kernel,
                         cudaFuncAttributeMaxDynamicSharedMemorySize, SMEM_GEMM_BYTES);

    gemm_lsm_kernel<<<(B_ * T_) / BM2, 256, SMEM_GEMM_BYTES>>>(F, W, bias);
    ctc_kernel<<<B_, 416>>>(labels, flens, llens);
    reduce_kernel<<<1, 32>>>(out);
}

// round 8
// speedup vs baseline: 1.8433x; 1.8433x over previous
#include <cuda_runtime.h>
#include <math.h>
#include <stdint.h>

#define B_    64
#define T_    1000
#define D_    512
#define V_    29
#define L_    200
#define S_    401            // 2*L + 1
#define CBLANK 28
#define NEGV  (-1e9f)
#define LOG2E 1.44269504088896340736f
#define LN2   0.69314718055994530942f

typedef unsigned long long u64;

// ---------------- device scratch (no allocations allowed) ----------------
__device__ float d_lp[(long)B_ * T_ * V_];   // LOG2-probs lp2[b][t][v], 7.4 MB
__device__ float d_loss[B_];

__device__ __forceinline__ float ex2f(float x){ float r; asm("ex2.approx.f32 %0, %1;" : "=f"(r) : "f"(x)); return r; }
__device__ __forceinline__ float lg2f(float x){ float r; asm("lg2.approx.f32 %0, %1;" : "=f"(r) : "f"(x)); return r; }

// exact 3-way log2-sum-exp via selects (no cancellation; NEGV-safe)
__device__ __forceinline__ float lse3(float a0, float a1, float a2)
{
    const float mab = fmaxf(a0, a1);
    const float nab = fminf(a0, a1);
    const float mx  = fmaxf(mab, a2);
    const float mn  = fminf(nab, a2);
    const float md  = fmaxf(nab, fminf(mab, a2));
    return mx + lg2f(1.0f + ex2f(mn - mx) + ex2f(md - mx));
}

#define FMA2(d, a, b) asm("fma.rn.f32x2 %0, %1, %2, %0;" : "+l"(d) : "l"(a), "l"(b))

// =====================================================================
// Kernel 1: logits = F @ W + b, log2_softmax, write d_lp.  (R7 verbatim)
// 256 threads, BM=256 rows/block (grid=250), thread tile 8 rows x 4 cols.
// F: cp.async double-buffered, row-major, XOR-swizzled smem.
// W: whole 512x32 transposed wT[col][k] (stride 516), resident in smem.
// FFMA2 pairs over k (lo=even-k, hi=odd-k partial sums).
// =====================================================================
#define BM2 256
#define WT_STRIDE 516
#define SMEM_GEMM_BYTES 132608

extern __shared__ char smem_dyn[];

__global__ __launch_bounds__(256, 1) void gemm_lsm_kernel(
    const float* __restrict__ F, const float* __restrict__ W,
    const float* __restrict__ bias)
{
    float* fbuf = (float*)smem_dyn;
    float* wT   = (float*)(smem_dyn + 65536);
    float* csh  = (float*)(smem_dyn + 131584);
    float* lbuf = fbuf;                         // epilogue reuse

    const int tid = threadIdx.x;
    const long rowBase = (long)blockIdx.x * BM2;
    const uint32_t fsh = (uint32_t)__cvta_generic_to_shared(fbuf);

    auto prefetch = [&](int kci, int st) {
        const uint32_t sbase = fsh + st * 32768u;
#pragma unroll
        for (int m = 0; m < 8; m++) {
            const int q  = tid + 256 * m;
            const int r  = q >> 3;
            const int kq = q & 7;
            const float* src = F + (rowBase + r) * D_ + kci * 32 + kq * 4;
            const uint32_t dst = sbase + (uint32_t)((r * 32 + ((kq ^ ((r >> 3) & 7)) << 2)) * 4);
            asm volatile("cp.async.ca.shared.global [%0], [%1], 16;" :: "r"(dst), "l"(src));
        }
    };

    prefetch(0, 0);
    asm volatile("cp.async.commit_group;");

    // one-time W transpose load (overlaps the first F prefetch)
    for (int idx = tid; idx < 512 * 32; idx += 256) {
        const int k = idx >> 5, c = idx & 31;
        wT[c * WT_STRIDE + k] = (c < V_) ? W[(long)k * V_ + c] : 0.f;
    }

    const int rg = tid >> 3;
    const int cg = tid & 7;
    const int fkey = (rg & 7) << 2;

    float bv[4];
#pragma unroll
    for (int j = 0; j < 4; j++) { int c = cg + 8 * j; bv[j] = (c < V_) ? bias[c] : 0.f; }

    u64 acc[8][4];
#pragma unroll
    for (int i = 0; i < 8; i++)
#pragma unroll
        for (int j = 0; j < 4; j++) acc[i][j] = 0ull;

    for (int kci = 0; kci < 16; kci++) {
        if (kci < 15) prefetch(kci + 1, (kci + 1) & 1);
        asm volatile("cp.async.commit_group;");
        asm volatile("cp.async.wait_group 1;");
        __syncthreads();

        const float* fstage = fbuf + (kci & 1) * 8192;
        const float* wbase  = wT + kci * 32;
#pragma unroll
        for (int kq = 0; kq < 8; kq++) {
            ulonglong2 f[8], w4[4];
#pragma unroll
            for (int i = 0; i < 8; i++)
                f[i] = *reinterpret_cast<const ulonglong2*>(
                    fstage + (rg * 8 + i) * 32 + ((kq << 2) ^ fkey));
#pragma unroll
            for (int j = 0; j < 4; j++)
                w4[j] = *reinterpret_cast<const ulonglong2*>(
                    wbase + (cg + 8 * j) * WT_STRIDE + kq * 4);
#pragma unroll
            for (int i = 0; i < 8; i++)
#pragma unroll
                for (int j = 0; j < 4; j++) FMA2(acc[i][j], f[i].x, w4[j].x);
#pragma unroll
            for (int i = 0; i < 8; i++)
#pragma unroll
                for (int j = 0; j < 4; j++) FMA2(acc[i][j], f[i].y, w4[j].y);
        }
        __syncthreads();
    }

    // ---- epilogue: combine k-pairs, bias, logits to smem [256][33] ----
#pragma unroll
    for (int i = 0; i < 8; i++)
#pragma unroll
        for (int j = 0; j < 4; j++) {
            const float lo = __uint_as_float((unsigned)(acc[i][j] & 0xffffffffull));
            const float hi = __uint_as_float((unsigned)(acc[i][j] >> 32));
            lbuf[(rg * 8 + i) * 33 + (cg + 8 * j)] = lo + hi + bv[j];
        }
    __syncthreads();

    // per-row (max*LOG2E + log2(sumexp)); thread <-> row
    {
        const float* r = &lbuf[tid * 33];
        float m = r[0];
#pragma unroll
        for (int v = 1; v < V_; v++) m = fmaxf(m, r[v]);
        float sum = 0.f;
#pragma unroll
        for (int v = 0; v < V_; v++) sum += ex2f((r[v] - m) * LOG2E);
        csh[tid] = m * LOG2E + lg2f(sum);
    }
    __syncthreads();

    // coalesced write of LOG2-probs
    float* outp = d_lp + rowBase * V_;
    for (int i = tid; i < BM2 * V_; i += 256) {
        const int row = i / V_;
        const int v   = i - row * V_;
        outp[i] = lbuf[row * 33 + v] * LOG2E - csh[row];
    }
}

// =====================================================================
// Kernel 2: CTC alpha recursion, LOG2 domain. One block per batch,
// 416 threads, thread s owns state s (own alpha in register).
// One __syncthreads per step; NO staging machinery: each thread
// prefetches its own lp value 8 steps ahead with a plain LDG (L1-hit).
// Branch-free inner loop; dummy lanes 401..415 compute harmless values.
// =====================================================================
__global__ __launch_bounds__(416) void ctc_kernel(
    const int* __restrict__ labels, const int* __restrict__ flens,
    const int* __restrict__ llens)
{
    __shared__ float abuf[2][420];      // idx = state + 4; pads [0..3] = NEGV
    __shared__ int   lab_sh[L_];

    const int b    = blockIdx.x;
    const int tid  = threadIdx.x;
    const int flen = flens[b];
    const int llen = llens[b];

    for (int i = tid; i < L_; i += 416) lab_sh[i] = labels[b * L_ + i];
    if (tid < 4) { abuf[0][tid] = NEGV; abuf[1][tid] = NEGV; }
    __syncthreads();

    const int s = tid;
    int   ext  = CBLANK;
    bool  skip = false;
    if (s < S_ && (s & 1)) {
        const int j = s >> 1;
        ext  = lab_sh[j];
        skip = (s >= 3) ? (ext != lab_sh[j - 1]) : true;
    }

    const float* lpb = d_lp + (long)b * T_ * V_;

    // t = 0 init
    float myA = NEGV;
    if (s == 0) myA = lpb[CBLANK];
    else if (s == 1) myA = lpb[ext];
    abuf[0][s + 4] = myA;

    // 8-deep per-thread lp prefetch: pf_k holds row t+k at loop entry (t=1)
    float pf0 = lpb[1 * V_ + ext];
    float pf1 = lpb[2 * V_ + ext];
    float pf2 = lpb[3 * V_ + ext];
    float pf3 = lpb[4 * V_ + ext];
    float pf4 = lpb[5 * V_ + ext];
    float pf5 = lpb[6 * V_ + ext];
    float pf6 = lpb[7 * V_ + ext];
    float pf7 = lpb[8 * V_ + ext];
    __syncthreads();

    int cur = 0;
    int t = 1;

#define CTC_STEP(PF) do {                                                        \
    const float am1 = abuf[cur][s + 3];                                          \
    const float am2 = abuf[cur][s + 2];                                          \
    myA = lse3(myA, am1, skip ? am2 : NEGV) + PF;                                \
    PF = lpb[min(t + 8, T_ - 1) * V_ + ext];                                     \
    abuf[cur ^ 1][s + 4] = myA;                                                  \
    cur ^= 1;                                                                    \
    __syncthreads();                                                             \
    t++;                                                                         \
} while (0)

    while (t + 7 < flen) {
        CTC_STEP(pf0); CTC_STEP(pf1); CTC_STEP(pf2); CTC_STEP(pf3);
        CTC_STEP(pf4); CTC_STEP(pf5); CTC_STEP(pf6); CTC_STEP(pf7);
    }
    while (t < flen) {
        CTC_STEP(pf0);
        pf0 = pf1; pf1 = pf2; pf2 = pf3; pf3 = pf4;
        pf4 = pf5; pf5 = pf6; pf6 = pf7;
    }
#undef CTC_STEP

    if (tid == 0) {
        const float l1 = abuf[cur][2 * llen + 4];    // alpha[2*llen]   (llen >= 50)
        const float l2 = abuf[cur][2 * llen + 3];    // alpha[2*llen-1]
        const float mx = fmaxf(l1, l2), mn = fminf(l1, l2);
        const float ls = mx + lg2f(1.0f + ex2f(mn - mx));
        const float nll = -ls * LN2;
        d_loss[b] = (nll < 5e8f) ? nll / (float)llen : 0.f;
    }
}

// =====================================================================
// Kernel 3: deterministic fixed-order mean of 64 losses
// =====================================================================
__global__ void reduce_kernel(float* __restrict__ out)
{
    const int lane = threadIdx.x;
    float v = d_loss[lane] + d_loss[lane + 32];
#pragma unroll
    for (int o = 16; o > 0; o >>= 1) v += __shfl_down_sync(0xffffffffu, v, o);
    if (lane == 0) out[0] = v * (1.f / (float)B_);
}

// =====================================================================
extern "C" void kernel_launch(void* const* d_in, const int* in_sizes, int n_in,
                              void* d_out, int out_size)
{
    (void)in_sizes; (void)n_in; (void)out_size;
    const float* F      = (const float*)d_in[0];
    const float* W      = (const float*)d_in[1];
    const float* bias   = (const float*)d_in[2];
    const int*   labels = (const int*)d_in[3];
    const int*   flens  = (const int*)d_in[4];
    const int*   llens  = (const int*)d_in[5];
    float* out = (float*)d_out;

    cudaFuncSetAttribute(gemm_lsm_kernel,
                         cudaFuncAttributeMaxDynamicSharedMemorySize, SMEM_GEMM_BYTES);

    gemm_lsm_kernel<<<(B_ * T_) / BM2, 256, SMEM_GEMM_BYTES>>>(F, W, bias);
    ctc_kernel<<<B_, 416>>>(labels, flens, llens);
    reduce_kernel<<<1, 32>>>(out);
}